// round 2
// baseline (speedup 1.0000x reference)
#include <cuda_runtime.h>
#include <math.h>

#define NB   2048
#define NT   1024
#define FEAT 10
#define TAU_ 10.0
#define K1_  1.0
#define DEL_ 0.1

#define CHUNKS 32
#define CLEN   32
#define TB     64          // tokens per MLP block (= 2 scan chunks)
#define NTOK   (NB*NT)

// scratch (allocation-free rule: __device__ globals)
__device__ float g_E[NB * CHUNKS * 2];
__device__ float g_X[NB * CHUNKS * 2];

struct Aff { float p00, p01, p10, p11, g0, g1; };

// ---------------------------------------------------------------------------
// Phase 1: per (b, chunk) local affine accumulation with zero init state
// ---------------------------------------------------------------------------
__global__ void scan_phase1(const float* __restrict__ in, Aff a) {
    int idx = blockIdx.x * blockDim.x + threadIdx.x;
    if (idx >= NB * CHUNKS) return;
    int b = idx / CHUNKS, c = idx % CHUNKS;
    const float* u = in + ((size_t)b * NT + (size_t)c * CLEN) * FEAT;
    float s0 = 0.f, s1 = 0.f;
    #pragma unroll 4
    for (int j = 0; j < CLEN; j++) {
        float uu = u[j * FEAT];
        float n0 = a.p00 * s0 + a.p01 * s1 + a.g0 * uu;
        float n1 = a.p10 * s0 + a.p11 * s1 + a.g1 * uu;
        s0 = n0; s1 = n1;
    }
    g_E[idx * 2 + 0] = s0;
    g_E[idx * 2 + 1] = s1;
}

// ---------------------------------------------------------------------------
// Phase 2: per-b prefix over chunks with PhiL = Phi^CLEN; writes chunk-start
// states into g_X
// ---------------------------------------------------------------------------
__global__ void scan_phase2(const float* __restrict__ x0, Aff aL) {
    int b = blockIdx.x * blockDim.x + threadIdx.x;
    if (b >= NB) return;
    float s0 = x0[b * 2 + 0], s1 = x0[b * 2 + 1];
    #pragma unroll 4
    for (int c = 0; c < CHUNKS; c++) {
        g_X[(b * CHUNKS + c) * 2 + 0] = s0;
        g_X[(b * CHUNKS + c) * 2 + 1] = s1;
        float e0 = g_E[(b * CHUNKS + c) * 2 + 0];
        float e1 = g_E[(b * CHUNKS + c) * 2 + 1];
        float n0 = aL.p00 * s0 + aL.p01 * s1 + e0;
        float n1 = aL.p10 * s0 + aL.p11 * s1 + e1;
        s0 = n0; s1 = n1;
    }
}

// ---------------------------------------------------------------------------
// Fused MLP + scan replay epilogue:
//   out[tok][c] = xG[tok][c] + (W3^T tanh(W2^T tanh(W1^T seq + b1) + b2))[c]
// Block: 128 threads, TB=64 tokens. W2 + H^T in shared, 8x8 register tile.
// ---------------------------------------------------------------------------
__global__ __launch_bounds__(128) void mlp_kernel(
    const float* __restrict__ in,
    const float* __restrict__ W1, const float* __restrict__ b1,
    const float* __restrict__ W2, const float* __restrict__ b2,
    const float* __restrict__ W3,
    float* __restrict__ out, Aff a)
{
    extern __shared__ float sm[];
    float* sW2 = sm;                   // [128][132]
    float* sH  = sW2 + 128 * 132;      // [128][68]  H1^T, later reused as H2^T
    float* sW1 = sH  + 128 * 68;       // [9][128]
    float* sIn = sW1 + 9 * 128;        // [64][10]
    float* sB1 = sIn + TB * FEAT;      // [128]
    float* sB2 = sB1 + 128;            // [128]
    float* sW3 = sB2 + 128;            // [128][2]

    const int tid = threadIdx.x;
    const size_t tok0 = (size_t)blockIdx.x * TB;

    // ---- stage weights + inputs ----
    {
        const float4* gW2 = (const float4*)W2;
        #pragma unroll 8
        for (int n = tid; n < 128 * 32; n += 128) {       // 4096 float4
            int i = n >> 5, j4 = n & 31;
            *(float4*)&sW2[i * 132 + j4 * 4] = gW2[n];
        }
        const float4* gIn = (const float4*)(in + tok0 * FEAT);
        for (int n = tid; n < (TB * FEAT) / 4; n += 128)  // 160 float4
            *(float4*)&sIn[n * 4] = gIn[n];
        for (int n = tid; n < 9 * 128; n += 128) sW1[n] = W1[n];
        sB1[tid] = b1[tid];
        sB2[tid] = b2[tid];
        for (int n = tid; n < 256; n += 128) sW3[n] = W3[n];
    }
    __syncthreads();

    // ---- layer 1: H1^T[i][tk] = tanh(b1[i] + sum_k seq[tk][k] * W1[k][i]) ----
    for (int n = tid; n < 128 * TB; n += 128) {
        int i = n >> 6, tk = n & 63;
        float acc = sB1[i];
        #pragma unroll
        for (int k = 0; k < 9; k++)
            acc += sIn[tk * FEAT + 1 + k] * sW1[k * 128 + i];
        sH[i * 68 + tk] = tanhf(acc);
    }
    __syncthreads();

    // ---- layer 2: 8 tokens x 8 outputs per thread ----
    const int tg = tid >> 4, jg = tid & 15;
    const int tk0 = tg * 8, j0 = jg * 8;
    float acc[8][8];
    #pragma unroll
    for (int p = 0; p < 8; p++)
        #pragma unroll
        for (int q = 0; q < 8; q++) acc[p][q] = 0.f;

    #pragma unroll 2
    for (int i = 0; i < 128; i++) {
        float4 ha = *(float4*)&sH[i * 68 + tk0];
        float4 hb = *(float4*)&sH[i * 68 + tk0 + 4];
        float4 wa = *(float4*)&sW2[i * 132 + j0];
        float4 wb = *(float4*)&sW2[i * 132 + j0 + 4];
        float h[8] = {ha.x, ha.y, ha.z, ha.w, hb.x, hb.y, hb.z, hb.w};
        float w[8] = {wa.x, wa.y, wa.z, wa.w, wb.x, wb.y, wb.z, wb.w};
        #pragma unroll
        for (int p = 0; p < 8; p++)
            #pragma unroll
            for (int q = 0; q < 8; q++)
                acc[p][q] += h[p] * w[q];
    }
    __syncthreads();   // everyone done reading sH before we overwrite it

    // ---- tanh + write H2^T back into sH ----
    #pragma unroll
    for (int q = 0; q < 8; q++) {
        float bb = sB2[j0 + q];
        #pragma unroll
        for (int p = 0; p < 8; p++)
            sH[(j0 + q) * 68 + (tk0 + p)] = tanhf(acc[p][q] + bb);
    }
    __syncthreads();

    // ---- layer 3 + fused scan replay epilogue ----
    {
        int tk = tid >> 1, c = tid & 1;
        float r = 0.f;
        #pragma unroll 8
        for (int j = 0; j < 128; j++)
            r += sH[j * 68 + tk] * sW3[j * 2 + c];

        // replay affine recurrence from chunk start to token tk
        int chunk = (int)(tok0 / CLEN) + (tk >> 5);   // global chunk index
        int jloc  = tk & (CLEN - 1);                  // steps to replay
        int ubase = tk & ~(CLEN - 1);                 // chunk-local first token in sIn
        float s0 = g_X[chunk * 2 + 0];
        float s1 = g_X[chunk * 2 + 1];
        for (int j = 0; j < jloc; j++) {
            float uu = sIn[(ubase + j) * FEAT];
            float n0 = a.p00 * s0 + a.p01 * s1 + a.g0 * uu;
            float n1 = a.p10 * s0 + a.p11 * s1 + a.g1 * uu;
            s0 = n0; s1 = n1;
        }
        float xg = c ? s1 : s0;
        out[(tok0 + tk) * 2 + c] = xg + r;
    }
}

// ---------------------------------------------------------------------------
// host: closed-form RK4 affine step for the linear ODE, in double
// ---------------------------------------------------------------------------
static void mat2_mul(const double A[2][2], const double B[2][2], double C[2][2]) {
    C[0][0] = A[0][0]*B[0][0] + A[0][1]*B[1][0];
    C[0][1] = A[0][0]*B[0][1] + A[0][1]*B[1][1];
    C[1][0] = A[1][0]*B[0][0] + A[1][1]*B[1][0];
    C[1][1] = A[1][0]*B[0][1] + A[1][1]*B[1][1];
}

extern "C" void kernel_launch(void* const* d_in, const int* in_sizes, int n_in,
                              void* d_out, int out_size) {
    const float* inp = (const float*)d_in[0];
    const float* x0  = (const float*)d_in[1];
    const float* W1  = (const float*)d_in[2];
    const float* b1  = (const float*)d_in[3];
    const float* W2  = (const float*)d_in[4];
    const float* b2  = (const float*)d_in[5];
    const float* W3  = (const float*)d_in[6];
    float* out = (float*)d_out;

    // Phi = sum_{k=0..4} (dA)^k / k!,  Gamma = d*(I + dA/2 + (dA)^2/6 + (dA)^3/24)*B
    double A[2][2] = {{-(1.0/TAU_ + K1_), 0.0}, {K1_, -1.0/TAU_}};
    double Bv[2]   = {1.0/TAU_, 0.0};
    double M[2][2] = {{DEL_*A[0][0], DEL_*A[0][1]}, {DEL_*A[1][0], DEL_*A[1][1]}};
    double M2[2][2], M3[2][2], M4[2][2];
    mat2_mul(M, M, M2); mat2_mul(M2, M, M3); mat2_mul(M3, M, M4);
    double Phi[2][2], G[2][2];
    for (int r = 0; r < 2; r++)
        for (int c = 0; c < 2; c++) {
            double id = (r == c) ? 1.0 : 0.0;
            Phi[r][c] = id + M[r][c] + M2[r][c]/2.0 + M3[r][c]/6.0 + M4[r][c]/24.0;
            G[r][c]   = DEL_ * (id + M[r][c]/2.0 + M2[r][c]/6.0 + M3[r][c]/24.0);
        }
    double Gam[2] = {G[0][0]*Bv[0] + G[0][1]*Bv[1], G[1][0]*Bv[0] + G[1][1]*Bv[1]};

    // PhiL = Phi^CLEN (CLEN = 32 -> 5 squarings)
    double PL[2][2] = {{Phi[0][0], Phi[0][1]}, {Phi[1][0], Phi[1][1]}};
    for (int s = 0; s < 5; s++) {
        double T[2][2];
        mat2_mul(PL, PL, T);
        PL[0][0]=T[0][0]; PL[0][1]=T[0][1]; PL[1][0]=T[1][0]; PL[1][1]=T[1][1];
    }

    Aff a  = {(float)Phi[0][0], (float)Phi[0][1], (float)Phi[1][0], (float)Phi[1][1],
              (float)Gam[0], (float)Gam[1]};
    Aff aL = {(float)PL[0][0], (float)PL[0][1], (float)PL[1][0], (float)PL[1][1], 0.f, 0.f};

    // blocked scan: chunk sums, then chunk-start states into g_X
    scan_phase1<<<(NB*CHUNKS + 255)/256, 256>>>(inp, a);
    scan_phase2<<<(NB + 255)/256, 256>>>(x0, aL);

    // fused MLP + scan replay epilogue
    const int smem = (128*132 + 128*68 + 9*128 + TB*FEAT + 128 + 128 + 256) * 4;
    cudaFuncSetAttribute(mlp_kernel, cudaFuncAttributeMaxDynamicSharedMemorySize, smem);
    mlp_kernel<<<NTOK / TB, 128, smem>>>(inp, W1, b1, W2, b2, W3, out, a);
}

// round 4
// speedup vs baseline: 3.5097x; 3.5097x over previous
#include <cuda_runtime.h>
#include <math.h>
#include <stdint.h>

#define NB   2048
#define NT   1024
#define FEAT 10
#define TAU_ 10.0
#define K1_  1.0
#define DEL_ 0.1

#define CHUNKS 32
#define CLEN   32
#define TB     256                 // tokens per tile (8 warps x 32 tokens)
#define NTOK   (NB*NT)
#define NTILES (NTOK/TB)           // 8192
#define GRID   148

// scratch (allocation-free rule: __device__ globals)
__device__ float g_E[NB * CHUNKS * 2];
__device__ float g_X[NB * CHUNKS * 2];

struct Aff { float p00, p01, p10, p11, g0, g1; };

// ---------------------------------------------------------------------------
// helpers
// ---------------------------------------------------------------------------
__device__ __forceinline__ uint32_t f2tf(float x) {           // round-to-nearest tf32
    uint32_t r;
    asm("cvt.rna.tf32.f32 %0, %1;" : "=r"(r) : "f"(x));
    return r;
}
__device__ __forceinline__ float f2tf_f(float x) { return __uint_as_float(f2tf(x)); }

__device__ __forceinline__ float fast_tanh(float x) {
    // tanh(x) = 1 - 2/(exp(2x)+1); ex2/rcp approx err ~1e-6
    float e, r;
    asm("ex2.approx.f32 %0, %1;" : "=f"(e) : "f"(x * 2.8853900817779268f));
    asm("rcp.approx.f32 %0, %1;" : "=f"(r) : "f"(e + 1.0f));
    return 1.0f - 2.0f * r;
}

__device__ __forceinline__ void mma_tf32(float* c, const uint32_t* a, uint32_t b0, uint32_t b1) {
    asm volatile(
        "mma.sync.aligned.m16n8k8.row.col.f32.tf32.tf32.f32 "
        "{%0,%1,%2,%3}, {%4,%5,%6,%7}, {%8,%9}, {%0,%1,%2,%3};"
        : "+f"(c[0]), "+f"(c[1]), "+f"(c[2]), "+f"(c[3])
        : "r"(a[0]), "r"(a[1]), "r"(a[2]), "r"(a[3]), "r"(b0), "r"(b1));
}

// ---------------------------------------------------------------------------
// scan phase 1/2 (blocked linear recurrence; tiny)
// ---------------------------------------------------------------------------
__global__ void scan_phase1(const float* __restrict__ in, Aff a) {
    int idx = blockIdx.x * blockDim.x + threadIdx.x;
    if (idx >= NB * CHUNKS) return;
    int b = idx / CHUNKS, c = idx % CHUNKS;
    const float* u = in + ((size_t)b * NT + (size_t)c * CLEN) * FEAT;
    float s0 = 0.f, s1 = 0.f;
    #pragma unroll 4
    for (int j = 0; j < CLEN; j++) {
        float uu = u[j * FEAT];
        float n0 = a.p00 * s0 + a.p01 * s1 + a.g0 * uu;
        float n1 = a.p10 * s0 + a.p11 * s1 + a.g1 * uu;
        s0 = n0; s1 = n1;
    }
    g_E[idx * 2 + 0] = s0;
    g_E[idx * 2 + 1] = s1;
}
__global__ void scan_phase2(const float* __restrict__ x0, Aff aL) {
    int b = blockIdx.x * blockDim.x + threadIdx.x;
    if (b >= NB) return;
    float s0 = x0[b * 2 + 0], s1 = x0[b * 2 + 1];
    #pragma unroll 4
    for (int c = 0; c < CHUNKS; c++) {
        g_X[(b * CHUNKS + c) * 2 + 0] = s0;
        g_X[(b * CHUNKS + c) * 2 + 1] = s1;
        float e0 = g_E[(b * CHUNKS + c) * 2 + 0];
        float e1 = g_E[(b * CHUNKS + c) * 2 + 1];
        float n0 = aL.p00 * s0 + aL.p01 * s1 + e0;
        float n1 = aL.p10 * s0 + aL.p11 * s1 + e1;
        s0 = n0; s1 = n1;
    }
}

// ---------------------------------------------------------------------------
// smem layout (float offsets)
// ---------------------------------------------------------------------------
#define SMF_H    0                        // [256][132]  h / h2 plane
#define SMF_W2   (SMF_H  + 256*132)       // [128 n][132] W2^T tf32
#define SMF_W1   (SMF_W2 + 128*132)       // [128 n][20]  W1^T tf32 (k<9, rest 0)
#define SMF_B1   (SMF_W1 + 128*20)
#define SMF_B2   (SMF_B1 + 128)
#define SMF_W3   (SMF_B2 + 128)           // [128][2]
#define SMF_TOT  (SMF_W3 + 256)           // 53760 floats = 215040 B

// ---------------------------------------------------------------------------
// Persistent fused MLP: tf32 mma.sync (layer1 + layer2) + MUFU tanh +
// SIMT layer3 + warp-scan epilogue.  8 warps, warp = 32 tokens = 1 chunk.
// ---------------------------------------------------------------------------
__global__ __launch_bounds__(256, 1) void mlp_kernel(
    const float* __restrict__ in,
    const float* __restrict__ W1, const float* __restrict__ b1,
    const float* __restrict__ W2, const float* __restrict__ b2,
    const float* __restrict__ W3,
    float* __restrict__ out, Aff a)
{
    extern __shared__ float sm[];
    const int tid  = threadIdx.x;
    const int w    = tid >> 5;
    const int lane = tid & 31;
    const int gid  = lane >> 2;      // 0..7
    const int tig  = lane & 3;       // 0..3
    const int wbase = w * 32;        // warp's first row in tile

    // ---- stage weights (once) ----
    for (int i = tid; i < 128 * 128; i += 256) {
        int k = i >> 7, n = i & 127;
        sm[SMF_W2 + n * 132 + k] = f2tf_f(W2[i]);          // W2[k][n] -> [n][k]
    }
    for (int i = tid; i < 128 * 20; i += 256) {
        int n = i / 20, k = i % 20;
        float v = (k < 9) ? W1[k * 128 + n] : 0.f;
        sm[SMF_W1 + n * 20 + k] = f2tf_f(v);
    }
    if (tid < 128) { sm[SMF_B1 + tid] = b1[tid]; sm[SMF_B2 + tid] = b2[tid]; }
    sm[SMF_W3 + tid] = W3[tid];
    __syncthreads();

    for (int tile = blockIdx.x; tile < NTILES; tile += GRID) {
        const size_t tok0 = (size_t)tile * TB;
        float acc[2][16][4];

        // ================= layer 1: [32 tok] x [128] = A[32x16] * W1 =========
        #pragma unroll
        for (int mt = 0; mt < 2; mt++)
            #pragma unroll
            for (int nt = 0; nt < 16; nt++) {
                float2 bb = *(const float2*)&sm[SMF_B1 + nt * 8 + 2 * tig];
                acc[mt][nt][0] = bb.x; acc[mt][nt][1] = bb.y;
                acc[mt][nt][2] = bb.x; acc[mt][nt][3] = bb.y;
            }
        #pragma unroll
        for (int kk = 0; kk < 2; kk++) {
            uint32_t afr[2][4];
            #pragma unroll
            for (int mt = 0; mt < 2; mt++) {
                size_t r0 = tok0 + wbase + mt * 16 + gid;
                int k0 = kk * 8 + tig;
                afr[mt][0] = (k0 < 9)     ? f2tf(in[r0 * FEAT + 1 + k0])            : 0u;
                afr[mt][1] = (k0 < 9)     ? f2tf(in[(r0 + 8) * FEAT + 1 + k0])      : 0u;
                afr[mt][2] = (k0 + 4 < 9) ? f2tf(in[r0 * FEAT + 5 + k0])            : 0u;
                afr[mt][3] = (k0 + 4 < 9) ? f2tf(in[(r0 + 8) * FEAT + 5 + k0])      : 0u;
            }
            #pragma unroll
            for (int nt = 0; nt < 16; nt++) {
                uint32_t b0 = __float_as_uint(sm[SMF_W1 + (nt * 8 + gid) * 20 + kk * 8 + tig]);
                uint32_t b1r = __float_as_uint(sm[SMF_W1 + (nt * 8 + gid) * 20 + kk * 8 + tig + 4]);
                mma_tf32(acc[0][nt], afr[0], b0, b1r);
                mma_tf32(acc[1][nt], afr[1], b0, b1r);
            }
        }
        // tanh -> tf32 -> sH
        #pragma unroll
        for (int mt = 0; mt < 2; mt++)
            #pragma unroll
            for (int nt = 0; nt < 16; nt++) {
                int ra = (wbase + mt * 16 + gid) * 132 + nt * 8 + 2 * tig;
                int rb = ra + 8 * 132;
                float2 va = make_float2(f2tf_f(fast_tanh(acc[mt][nt][0])),
                                        f2tf_f(fast_tanh(acc[mt][nt][1])));
                float2 vb = make_float2(f2tf_f(fast_tanh(acc[mt][nt][2])),
                                        f2tf_f(fast_tanh(acc[mt][nt][3])));
                *(float2*)&sm[SMF_H + ra] = va;
                *(float2*)&sm[SMF_H + rb] = vb;
            }
        __syncwarp();

        // ================= layer 2: [32 tok] x [128] = H[32x128] * W2 ========
        #pragma unroll
        for (int mt = 0; mt < 2; mt++)
            #pragma unroll
            for (int nt = 0; nt < 16; nt++) {
                float2 bb = *(const float2*)&sm[SMF_B2 + nt * 8 + 2 * tig];
                acc[mt][nt][0] = bb.x; acc[mt][nt][1] = bb.y;
                acc[mt][nt][2] = bb.x; acc[mt][nt][3] = bb.y;
            }
        #pragma unroll 4
        for (int kk = 0; kk < 16; kk++) {
            uint32_t afr[2][4];
            #pragma unroll
            for (int mt = 0; mt < 2; mt++) {
                int rr = (wbase + mt * 16 + gid) * 132 + kk * 8 + tig;
                afr[mt][0] = __float_as_uint(sm[SMF_H + rr]);
                afr[mt][1] = __float_as_uint(sm[SMF_H + rr + 8 * 132]);
                afr[mt][2] = __float_as_uint(sm[SMF_H + rr + 4]);
                afr[mt][3] = __float_as_uint(sm[SMF_H + rr + 8 * 132 + 4]);
            }
            #pragma unroll
            for (int nt = 0; nt < 16; nt++) {
                uint32_t b0 = __float_as_uint(sm[SMF_W2 + (nt * 8 + gid) * 132 + kk * 8 + tig]);
                uint32_t b1r = __float_as_uint(sm[SMF_W2 + (nt * 8 + gid) * 132 + kk * 8 + tig + 4]);
                mma_tf32(acc[0][nt], afr[0], b0, b1r);
                mma_tf32(acc[1][nt], afr[1], b0, b1r);
            }
        }
        __syncwarp();
        // tanh -> f32 h2 -> sH (in place, same warp rows)
        #pragma unroll
        for (int mt = 0; mt < 2; mt++)
            #pragma unroll
            for (int nt = 0; nt < 16; nt++) {
                int ra = (wbase + mt * 16 + gid) * 132 + nt * 8 + 2 * tig;
                int rb = ra + 8 * 132;
                *(float2*)&sm[SMF_H + ra] = make_float2(fast_tanh(acc[mt][nt][0]),
                                                        fast_tanh(acc[mt][nt][1]));
                *(float2*)&sm[SMF_H + rb] = make_float2(fast_tanh(acc[mt][nt][2]),
                                                        fast_tanh(acc[mt][nt][3]));
            }
        __syncwarp();

        // ================= layer 3 + warp-scan epilogue ======================
        {
            int row = wbase + lane;                 // my token (tile-local)
            size_t tok = tok0 + row;
            float r0 = 0.f, r1 = 0.f;
            const float4* hrow = (const float4*)&sm[SMF_H + row * 132];
            const float4* w34  = (const float4*)&sm[SMF_W3];
            #pragma unroll
            for (int q = 0; q < 32; q++) {
                float4 h4 = hrow[q];
                float4 wa = w34[2 * q];
                float4 wb = w34[2 * q + 1];
                r0 += h4.x * wa.x + h4.y * wa.z + h4.z * wb.x + h4.w * wb.z;
                r1 += h4.x * wa.y + h4.y * wa.w + h4.z * wb.y + h4.w * wb.w;
            }

            // affine warp scan over this chunk (warp == chunk)
            float uu = in[tok * FEAT];
            float m00 = a.p00, m01 = a.p01, m10 = a.p10, m11 = a.p11;
            float v0 = a.g0 * uu, v1 = a.g1 * uu;
            #pragma unroll
            for (int d = 1; d < 32; d <<= 1) {
                float pm00 = __shfl_up_sync(0xffffffffu, m00, d);
                float pm01 = __shfl_up_sync(0xffffffffu, m01, d);
                float pm10 = __shfl_up_sync(0xffffffffu, m10, d);
                float pm11 = __shfl_up_sync(0xffffffffu, m11, d);
                float pv0  = __shfl_up_sync(0xffffffffu, v0, d);
                float pv1  = __shfl_up_sync(0xffffffffu, v1, d);
                if (lane >= d) {
                    float n00 = m00 * pm00 + m01 * pm10;
                    float n01 = m00 * pm01 + m01 * pm11;
                    float n10 = m10 * pm00 + m11 * pm10;
                    float n11 = m10 * pm01 + m11 * pm11;
                    float nv0 = m00 * pv0 + m01 * pv1 + v0;
                    float nv1 = m10 * pv0 + m11 * pv1 + v1;
                    m00 = n00; m01 = n01; m10 = n10; m11 = n11;
                    v0 = nv0; v1 = nv1;
                }
            }
            // exclusive: shift by 1; lane 0 = identity
            float e00 = __shfl_up_sync(0xffffffffu, m00, 1);
            float e01 = __shfl_up_sync(0xffffffffu, m01, 1);
            float e10 = __shfl_up_sync(0xffffffffu, m10, 1);
            float e11 = __shfl_up_sync(0xffffffffu, m11, 1);
            float ev0 = __shfl_up_sync(0xffffffffu, v0, 1);
            float ev1 = __shfl_up_sync(0xffffffffu, v1, 1);
            if (lane == 0) { e00 = 1.f; e01 = 0.f; e10 = 0.f; e11 = 1.f; ev0 = 0.f; ev1 = 0.f; }

            int chunk = tile * 8 + w;
            float2 xs = *(const float2*)&g_X[chunk * 2];
            float s0 = e00 * xs.x + e01 * xs.y + ev0;
            float s1 = e10 * xs.x + e11 * xs.y + ev1;

            *(float2*)&out[tok * 2] = make_float2(s0 + r0, s1 + r1);
        }
        __syncwarp();   // sH rows reused next tile by this warp
    }
}

// ---------------------------------------------------------------------------
// host: closed-form RK4 affine step (linear ODE), double precision
// ---------------------------------------------------------------------------
static void mat2_mul(const double A[2][2], const double B[2][2], double C[2][2]) {
    C[0][0] = A[0][0]*B[0][0] + A[0][1]*B[1][0];
    C[0][1] = A[0][0]*B[0][1] + A[0][1]*B[1][1];
    C[1][0] = A[1][0]*B[0][0] + A[1][1]*B[1][0];
    C[1][1] = A[1][0]*B[0][1] + A[1][1]*B[1][1];
}

extern "C" void kernel_launch(void* const* d_in, const int* in_sizes, int n_in,
                              void* d_out, int out_size) {
    const float* inp = (const float*)d_in[0];
    const float* x0  = (const float*)d_in[1];
    const float* W1  = (const float*)d_in[2];
    const float* b1  = (const float*)d_in[3];
    const float* W2  = (const float*)d_in[4];
    const float* b2  = (const float*)d_in[5];
    const float* W3  = (const float*)d_in[6];
    float* out = (float*)d_out;

    double A[2][2] = {{-(1.0/TAU_ + K1_), 0.0}, {K1_, -1.0/TAU_}};
    double Bv[2]   = {1.0/TAU_, 0.0};
    double M[2][2] = {{DEL_*A[0][0], DEL_*A[0][1]}, {DEL_*A[1][0], DEL_*A[1][1]}};
    double M2[2][2], M3[2][2], M4[2][2];
    mat2_mul(M, M, M2); mat2_mul(M2, M, M3); mat2_mul(M3, M, M4);
    double Phi[2][2], G[2][2];
    for (int r = 0; r < 2; r++)
        for (int c = 0; c < 2; c++) {
            double id = (r == c) ? 1.0 : 0.0;
            Phi[r][c] = id + M[r][c] + M2[r][c]/2.0 + M3[r][c]/6.0 + M4[r][c]/24.0;
            G[r][c]   = DEL_ * (id + M[r][c]/2.0 + M2[r][c]/6.0 + M3[r][c]/24.0);
        }
    double Gam[2] = {G[0][0]*Bv[0] + G[0][1]*Bv[1], G[1][0]*Bv[0] + G[1][1]*Bv[1]};

    double PL[2][2] = {{Phi[0][0], Phi[0][1]}, {Phi[1][0], Phi[1][1]}};
    for (int s = 0; s < 5; s++) {
        double T[2][2];
        mat2_mul(PL, PL, T);
        PL[0][0]=T[0][0]; PL[0][1]=T[0][1]; PL[1][0]=T[1][0]; PL[1][1]=T[1][1];
    }

    Aff a  = {(float)Phi[0][0], (float)Phi[0][1], (float)Phi[1][0], (float)Phi[1][1],
              (float)Gam[0], (float)Gam[1]};
    Aff aL = {(float)PL[0][0], (float)PL[0][1], (float)PL[1][0], (float)PL[1][1], 0.f, 0.f};

    scan_phase1<<<(NB*CHUNKS + 255)/256, 256>>>(inp, a);
    scan_phase2<<<(NB + 255)/256, 256>>>(x0, aL);

    cudaFuncSetAttribute(mlp_kernel, cudaFuncAttributeMaxDynamicSharedMemorySize,
                         SMF_TOT * (int)sizeof(float));
    mlp_kernel<<<GRID, 256, SMF_TOT * sizeof(float)>>>(inp, W1, b1, W2, b2, W3, out, a);
}

// round 5
// speedup vs baseline: 5.1184x; 1.4584x over previous
#include <cuda_runtime.h>
#include <math.h>
#include <stdint.h>

#define NB   2048
#define NT   1024
#define FEAT 10
#define TAU_ 10.0
#define K1_  1.0
#define DEL_ 0.1

#define CHUNKS 32
#define CLEN   32
#define TB     256                 // tokens per tile (8 warps x 32 tokens)
#define NTOK   (NB*NT)
#define NTILES (NTOK/TB)           // 8192
#define GRID   148

// scratch (allocation-free rule: __device__ globals)
__device__ float g_E[NB * CHUNKS * 2];
__device__ float g_X[NB * CHUNKS * 2];

struct Aff { float p00, p01, p10, p11, g0, g1; };

// ---------------------------------------------------------------------------
// helpers
// ---------------------------------------------------------------------------
__device__ __forceinline__ uint32_t f2tf(float x) {           // round-to-nearest tf32
    uint32_t r;
    asm("cvt.rna.tf32.f32 %0, %1;" : "=r"(r) : "f"(x));
    return r;
}
__device__ __forceinline__ float f2tf_f(float x) { return __uint_as_float(f2tf(x)); }

__device__ __forceinline__ float fast_tanh(float x) {         // MUFU.TANH, 1 instr
    float r;
    asm("tanh.approx.f32 %0, %1;" : "=f"(r) : "f"(x));
    return r;
}

__device__ __forceinline__ void mma_tf32(float* c, const uint32_t* a, uint32_t b0, uint32_t b1) {
    asm volatile(
        "mma.sync.aligned.m16n8k8.row.col.f32.tf32.tf32.f32 "
        "{%0,%1,%2,%3}, {%4,%5,%6,%7}, {%8,%9}, {%0,%1,%2,%3};"
        : "+f"(c[0]), "+f"(c[1]), "+f"(c[2]), "+f"(c[3])
        : "r"(a[0]), "r"(a[1]), "r"(a[2]), "r"(a[3]), "r"(b0), "r"(b1));
}

// ---------------------------------------------------------------------------
// scan phase 1/2 (blocked linear recurrence; tiny)
// ---------------------------------------------------------------------------
__global__ void scan_phase1(const float* __restrict__ in, Aff a) {
    int idx = blockIdx.x * blockDim.x + threadIdx.x;
    if (idx >= NB * CHUNKS) return;
    int b = idx / CHUNKS, c = idx % CHUNKS;
    const float* u = in + ((size_t)b * NT + (size_t)c * CLEN) * FEAT;
    float s0 = 0.f, s1 = 0.f;
    #pragma unroll 4
    for (int j = 0; j < CLEN; j++) {
        float uu = u[j * FEAT];
        float n0 = a.p00 * s0 + a.p01 * s1 + a.g0 * uu;
        float n1 = a.p10 * s0 + a.p11 * s1 + a.g1 * uu;
        s0 = n0; s1 = n1;
    }
    g_E[idx * 2 + 0] = s0;
    g_E[idx * 2 + 1] = s1;
}
__global__ void scan_phase2(const float* __restrict__ x0, Aff aL) {
    int b = blockIdx.x * blockDim.x + threadIdx.x;
    if (b >= NB) return;
    float s0 = x0[b * 2 + 0], s1 = x0[b * 2 + 1];
    #pragma unroll 4
    for (int c = 0; c < CHUNKS; c++) {
        g_X[(b * CHUNKS + c) * 2 + 0] = s0;
        g_X[(b * CHUNKS + c) * 2 + 1] = s1;
        float e0 = g_E[(b * CHUNKS + c) * 2 + 0];
        float e1 = g_E[(b * CHUNKS + c) * 2 + 1];
        float n0 = aL.p00 * s0 + aL.p01 * s1 + e0;
        float n1 = aL.p10 * s0 + aL.p11 * s1 + e1;
        s0 = n0; s1 = n1;
    }
}

// ---------------------------------------------------------------------------
// smem layout (float offsets)
// W1/W2 use "packed-pair" order within each k-octet: original k = kk*8 + t,
// stored at pos = kk*8 + (t&3)*2 + (t>>2), so the mma B-fragment pair
// (k = kk*8+tig, k+4) is adjacent -> one float2 LDS. Row strides 136/24
// make the float2 loads bank-conflict-free (8*gid+2*tig distinct mod 32).
// ---------------------------------------------------------------------------
#define SMF_H    0                        // [256][132]  h / h2 plane
#define SMF_W2   (SMF_H  + 256*132)       // [128 n][136] W2^T tf32 packed
#define SMF_W1   (SMF_W2 + 128*136)       // [128 n][24]  W1^T tf32 packed (k<9, rest 0)
#define SMF_B1   (SMF_W1 + 128*24)
#define SMF_B2   (SMF_B1 + 128)
#define SMF_W3   (SMF_B2 + 128)           // [128][2]
#define SMF_TOT  (SMF_W3 + 256)           // 54784 floats = 219136 B

// ---------------------------------------------------------------------------
// Persistent fused MLP: tf32 mma.sync (layer1 + layer2) + MUFU.TANH +
// SIMT layer3 + warp-scan epilogue.  8 warps, warp = 32 tokens = 1 chunk.
// ---------------------------------------------------------------------------
__global__ __launch_bounds__(256, 1) void mlp_kernel(
    const float* __restrict__ in,
    const float* __restrict__ W1, const float* __restrict__ b1,
    const float* __restrict__ W2, const float* __restrict__ b2,
    const float* __restrict__ W3,
    float* __restrict__ out, Aff a)
{
    extern __shared__ float sm[];
    const int tid  = threadIdx.x;
    const int w    = tid >> 5;
    const int lane = tid & 31;
    const int gid  = lane >> 2;      // 0..7
    const int tig  = lane & 3;       // 0..3
    const int wbase = w * 32;        // warp's first row in tile

    // ---- stage weights (once) ----
    for (int i = tid; i < 128 * 128; i += 256) {
        int k = i >> 7, n = i & 127;
        int pos = (k & ~7) + ((k & 3) * 2) + ((k >> 2) & 1);
        sm[SMF_W2 + n * 136 + pos] = f2tf_f(W2[i]);        // W2[k][n] -> [n][pos]
    }
    for (int i = tid; i < 128 * 16; i += 256) {
        int n = i >> 4, k = i & 15;
        int pos = (k & ~7) + ((k & 3) * 2) + ((k >> 2) & 1);
        float v = (k < 9) ? W1[k * 128 + n] : 0.f;
        sm[SMF_W1 + n * 24 + pos] = f2tf_f(v);
    }
    if (tid < 128) { sm[SMF_B1 + tid] = b1[tid]; sm[SMF_B2 + tid] = b2[tid]; }
    sm[SMF_W3 + tid] = W3[tid];
    __syncthreads();

    for (int tile = blockIdx.x; tile < NTILES; tile += GRID) {
        const size_t tok0 = (size_t)tile * TB;
        float acc[2][16][4];

        // ================= layer 1: [32 tok] x [128] = A[32x16] * W1 =========
        #pragma unroll
        for (int mt = 0; mt < 2; mt++)
            #pragma unroll
            for (int nt = 0; nt < 16; nt++) {
                float2 bb = *(const float2*)&sm[SMF_B1 + nt * 8 + 2 * tig];
                acc[mt][nt][0] = bb.x; acc[mt][nt][1] = bb.y;
                acc[mt][nt][2] = bb.x; acc[mt][nt][3] = bb.y;
            }
        #pragma unroll
        for (int kk = 0; kk < 2; kk++) {
            uint32_t afr[2][4];
            #pragma unroll
            for (int mt = 0; mt < 2; mt++) {
                size_t r0 = tok0 + wbase + mt * 16 + gid;
                int k0 = kk * 8 + tig;
                afr[mt][0] = (k0 < 9)     ? f2tf(in[r0 * FEAT + 1 + k0])            : 0u;
                afr[mt][1] = (k0 < 9)     ? f2tf(in[(r0 + 8) * FEAT + 1 + k0])      : 0u;
                afr[mt][2] = (k0 + 4 < 9) ? f2tf(in[r0 * FEAT + 5 + k0])            : 0u;
                afr[mt][3] = (k0 + 4 < 9) ? f2tf(in[(r0 + 8) * FEAT + 5 + k0])      : 0u;
            }
            #pragma unroll
            for (int nt = 0; nt < 16; nt++) {
                float2 bp = *(const float2*)&sm[SMF_W1 + (nt * 8 + gid) * 24 + kk * 8 + 2 * tig];
                uint32_t b0 = __float_as_uint(bp.x);
                uint32_t b1r = __float_as_uint(bp.y);
                mma_tf32(acc[0][nt], afr[0], b0, b1r);
                mma_tf32(acc[1][nt], afr[1], b0, b1r);
            }
        }
        // tanh -> tf32 -> sH
        #pragma unroll
        for (int mt = 0; mt < 2; mt++)
            #pragma unroll
            for (int nt = 0; nt < 16; nt++) {
                int ra = (wbase + mt * 16 + gid) * 132 + nt * 8 + 2 * tig;
                int rb = ra + 8 * 132;
                float2 va = make_float2(f2tf_f(fast_tanh(acc[mt][nt][0])),
                                        f2tf_f(fast_tanh(acc[mt][nt][1])));
                float2 vb = make_float2(f2tf_f(fast_tanh(acc[mt][nt][2])),
                                        f2tf_f(fast_tanh(acc[mt][nt][3])));
                *(float2*)&sm[SMF_H + ra] = va;
                *(float2*)&sm[SMF_H + rb] = vb;
            }
        __syncwarp();

        // ================= layer 2: [32 tok] x [128] = H[32x128] * W2 ========
        #pragma unroll
        for (int mt = 0; mt < 2; mt++)
            #pragma unroll
            for (int nt = 0; nt < 16; nt++) {
                float2 bb = *(const float2*)&sm[SMF_B2 + nt * 8 + 2 * tig];
                acc[mt][nt][0] = bb.x; acc[mt][nt][1] = bb.y;
                acc[mt][nt][2] = bb.x; acc[mt][nt][3] = bb.y;
            }
        #pragma unroll 4
        for (int kk = 0; kk < 16; kk++) {
            uint32_t afr[2][4];
            #pragma unroll
            for (int mt = 0; mt < 2; mt++) {
                int rr = (wbase + mt * 16 + gid) * 132 + kk * 8 + tig;
                afr[mt][0] = __float_as_uint(sm[SMF_H + rr]);
                afr[mt][1] = __float_as_uint(sm[SMF_H + rr + 8 * 132]);
                afr[mt][2] = __float_as_uint(sm[SMF_H + rr + 4]);
                afr[mt][3] = __float_as_uint(sm[SMF_H + rr + 8 * 132 + 4]);
            }
            #pragma unroll
            for (int nt = 0; nt < 16; nt++) {
                float2 bp = *(const float2*)&sm[SMF_W2 + (nt * 8 + gid) * 136 + kk * 8 + 2 * tig];
                uint32_t b0 = __float_as_uint(bp.x);
                uint32_t b1r = __float_as_uint(bp.y);
                mma_tf32(acc[0][nt], afr[0], b0, b1r);
                mma_tf32(acc[1][nt], afr[1], b0, b1r);
            }
        }
        __syncwarp();
        // tanh -> f32 h2 -> sH (in place, same warp rows)
        #pragma unroll
        for (int mt = 0; mt < 2; mt++)
            #pragma unroll
            for (int nt = 0; nt < 16; nt++) {
                int ra = (wbase + mt * 16 + gid) * 132 + nt * 8 + 2 * tig;
                int rb = ra + 8 * 132;
                *(float2*)&sm[SMF_H + ra] = make_float2(fast_tanh(acc[mt][nt][0]),
                                                        fast_tanh(acc[mt][nt][1]));
                *(float2*)&sm[SMF_H + rb] = make_float2(fast_tanh(acc[mt][nt][2]),
                                                        fast_tanh(acc[mt][nt][3]));
            }
        __syncwarp();

        // ================= layer 3 + warp-scan epilogue ======================
        {
            int row = wbase + lane;                 // my token (tile-local)
            size_t tok = tok0 + row;
            float r0 = 0.f, r1 = 0.f;
            const float4* hrow = (const float4*)&sm[SMF_H + row * 132];
            const float4* w34  = (const float4*)&sm[SMF_W3];
            #pragma unroll
            for (int q = 0; q < 32; q++) {
                float4 h4 = hrow[q];
                float4 wa = w34[2 * q];
                float4 wb = w34[2 * q + 1];
                r0 += h4.x * wa.x + h4.y * wa.z + h4.z * wb.x + h4.w * wb.z;
                r1 += h4.x * wa.y + h4.y * wa.w + h4.z * wb.y + h4.w * wb.w;
            }

            // affine warp scan over this chunk (warp == chunk)
            float uu = in[tok * FEAT];
            float m00 = a.p00, m01 = a.p01, m10 = a.p10, m11 = a.p11;
            float v0 = a.g0 * uu, v1 = a.g1 * uu;
            #pragma unroll
            for (int d = 1; d < 32; d <<= 1) {
                float pm00 = __shfl_up_sync(0xffffffffu, m00, d);
                float pm01 = __shfl_up_sync(0xffffffffu, m01, d);
                float pm10 = __shfl_up_sync(0xffffffffu, m10, d);
                float pm11 = __shfl_up_sync(0xffffffffu, m11, d);
                float pv0  = __shfl_up_sync(0xffffffffu, v0, d);
                float pv1  = __shfl_up_sync(0xffffffffu, v1, d);
                if (lane >= d) {
                    float n00 = m00 * pm00 + m01 * pm10;
                    float n01 = m00 * pm01 + m01 * pm11;
                    float n10 = m10 * pm00 + m11 * pm10;
                    float n11 = m10 * pm01 + m11 * pm11;
                    float nv0 = m00 * pv0 + m01 * pv1 + v0;
                    float nv1 = m10 * pv0 + m11 * pv1 + v1;
                    m00 = n00; m01 = n01; m10 = n10; m11 = n11;
                    v0 = nv0; v1 = nv1;
                }
            }
            // exclusive: shift by 1; lane 0 = identity
            float e00 = __shfl_up_sync(0xffffffffu, m00, 1);
            float e01 = __shfl_up_sync(0xffffffffu, m01, 1);
            float e10 = __shfl_up_sync(0xffffffffu, m10, 1);
            float e11 = __shfl_up_sync(0xffffffffu, m11, 1);
            float ev0 = __shfl_up_sync(0xffffffffu, v0, 1);
            float ev1 = __shfl_up_sync(0xffffffffu, v1, 1);
            if (lane == 0) { e00 = 1.f; e01 = 0.f; e10 = 0.f; e11 = 1.f; ev0 = 0.f; ev1 = 0.f; }

            int chunk = tile * 8 + w;
            float2 xs = *(const float2*)&g_X[chunk * 2];
            float s0 = e00 * xs.x + e01 * xs.y + ev0;
            float s1 = e10 * xs.x + e11 * xs.y + ev1;

            *(float2*)&out[tok * 2] = make_float2(s0 + r0, s1 + r1);
        }
        __syncwarp();   // sH rows reused next tile by this warp
    }
}

// ---------------------------------------------------------------------------
// host: closed-form RK4 affine step (linear ODE), double precision
// ---------------------------------------------------------------------------
static void mat2_mul(const double A[2][2], const double B[2][2], double C[2][2]) {
    C[0][0] = A[0][0]*B[0][0] + A[0][1]*B[1][0];
    C[0][1] = A[0][0]*B[0][1] + A[0][1]*B[1][1];
    C[1][0] = A[1][0]*B[0][0] + A[1][1]*B[1][0];
    C[1][1] = A[1][0]*B[0][1] + A[1][1]*B[1][1];
}

extern "C" void kernel_launch(void* const* d_in, const int* in_sizes, int n_in,
                              void* d_out, int out_size) {
    const float* inp = (const float*)d_in[0];
    const float* x0  = (const float*)d_in[1];
    const float* W1  = (const float*)d_in[2];
    const float* b1  = (const float*)d_in[3];
    const float* W2  = (const float*)d_in[4];
    const float* b2  = (const float*)d_in[5];
    const float* W3  = (const float*)d_in[6];
    float* out = (float*)d_out;

    double A[2][2] = {{-(1.0/TAU_ + K1_), 0.0}, {K1_, -1.0/TAU_}};
    double Bv[2]   = {1.0/TAU_, 0.0};
    double M[2][2] = {{DEL_*A[0][0], DEL_*A[0][1]}, {DEL_*A[1][0], DEL_*A[1][1]}};
    double M2[2][2], M3[2][2], M4[2][2];
    mat2_mul(M, M, M2); mat2_mul(M2, M, M3); mat2_mul(M3, M, M4);
    double Phi[2][2], G[2][2];
    for (int r = 0; r < 2; r++)
        for (int c = 0; c < 2; c++) {
            double id = (r == c) ? 1.0 : 0.0;
            Phi[r][c] = id + M[r][c] + M2[r][c]/2.0 + M3[r][c]/6.0 + M4[r][c]/24.0;
            G[r][c]   = DEL_ * (id + M[r][c]/2.0 + M2[r][c]/6.0 + M3[r][c]/24.0);
        }
    double Gam[2] = {G[0][0]*Bv[0] + G[0][1]*Bv[1], G[1][0]*Bv[0] + G[1][1]*Bv[1]};

    double PL[2][2] = {{Phi[0][0], Phi[0][1]}, {Phi[1][0], Phi[1][1]}};
    for (int s = 0; s < 5; s++) {
        double T[2][2];
        mat2_mul(PL, PL, T);
        PL[0][0]=T[0][0]; PL[0][1]=T[0][1]; PL[1][0]=T[1][0]; PL[1][1]=T[1][1];
    }

    Aff a  = {(float)Phi[0][0], (float)Phi[0][1], (float)Phi[1][0], (float)Phi[1][1],
              (float)Gam[0], (float)Gam[1]};
    Aff aL = {(float)PL[0][0], (float)PL[0][1], (float)PL[1][0], (float)PL[1][1], 0.f, 0.f};

    scan_phase1<<<(NB*CHUNKS + 255)/256, 256>>>(inp, a);
    scan_phase2<<<(NB + 255)/256, 256>>>(x0, aL);

    cudaFuncSetAttribute(mlp_kernel, cudaFuncAttributeMaxDynamicSharedMemorySize,
                         SMF_TOT * (int)sizeof(float));
    mlp_kernel<<<GRID, 256, SMF_TOT * sizeof(float)>>>(inp, W1, b1, W2, b2, W3, out, a);
}

// round 6
// speedup vs baseline: 8.7057x; 1.7009x over previous
#include <cuda_runtime.h>
#include <cuda_fp16.h>
#include <math.h>
#include <stdint.h>

#define NB   2048
#define NT   1024
#define FEAT 10
#define TAU_ 10.0
#define K1_  1.0
#define DEL_ 0.1

#define CHUNKS 32
#define CLEN   32
#define TB     256                 // tokens per tile (8 warps x 32 tokens)
#define NTOK   (NB*NT)
#define NTILES (NTOK/TB)           // 8192
#define GRID   148

__device__ float g_E[NB * CHUNKS * 2];
__device__ float g_X[NB * CHUNKS * 2];

struct Aff { float p00, p01, p10, p11, g0, g1; };

// ---------------------------------------------------------------------------
// helpers
// ---------------------------------------------------------------------------
__device__ __forceinline__ uint32_t pack_h2(float lo, float hi) {
    __half2 h = __float22half2_rn(make_float2(lo, hi));   // .x = lo half
    return *(uint32_t*)&h;
}
__device__ __forceinline__ uint32_t tanh_h2(uint32_t x) {
    uint32_t r;
    asm("tanh.approx.f16x2 %0, %1;" : "=r"(r) : "r"(x));
    return r;
}
__device__ __forceinline__ float fast_tanh(float x) {
    float r;
    asm("tanh.approx.f32 %0, %1;" : "=f"(r) : "f"(x));
    return r;
}
__device__ __forceinline__ void mma_f16(float* c, uint32_t a0, uint32_t a1,
                                        uint32_t a2, uint32_t a3,
                                        uint32_t b0, uint32_t b1) {
    asm volatile(
        "mma.sync.aligned.m16n8k16.row.col.f32.f16.f16.f32 "
        "{%0,%1,%2,%3}, {%4,%5,%6,%7}, {%8,%9}, {%0,%1,%2,%3};"
        : "+f"(c[0]), "+f"(c[1]), "+f"(c[2]), "+f"(c[3])
        : "r"(a0), "r"(a1), "r"(a2), "r"(a3), "r"(b0), "r"(b1));
}

// ---------------------------------------------------------------------------
// scan phase 1/2 (blocked linear recurrence; tiny)
// ---------------------------------------------------------------------------
__global__ void scan_phase1(const float* __restrict__ in, Aff a) {
    int idx = blockIdx.x * blockDim.x + threadIdx.x;
    if (idx >= NB * CHUNKS) return;
    int b = idx / CHUNKS, c = idx % CHUNKS;
    const float* u = in + ((size_t)b * NT + (size_t)c * CLEN) * FEAT;
    float s0 = 0.f, s1 = 0.f;
    #pragma unroll 4
    for (int j = 0; j < CLEN; j++) {
        float uu = u[j * FEAT];
        float n0 = a.p00 * s0 + a.p01 * s1 + a.g0 * uu;
        float n1 = a.p10 * s0 + a.p11 * s1 + a.g1 * uu;
        s0 = n0; s1 = n1;
    }
    g_E[idx * 2 + 0] = s0;
    g_E[idx * 2 + 1] = s1;
}
__global__ void scan_phase2(const float* __restrict__ x0, Aff aL) {
    int b = blockIdx.x * blockDim.x + threadIdx.x;
    if (b >= NB) return;
    float s0 = x0[b * 2 + 0], s1 = x0[b * 2 + 1];
    #pragma unroll 4
    for (int c = 0; c < CHUNKS; c++) {
        g_X[(b * CHUNKS + c) * 2 + 0] = s0;
        g_X[(b * CHUNKS + c) * 2 + 1] = s1;
        float e0 = g_E[(b * CHUNKS + c) * 2 + 0];
        float e1 = g_E[(b * CHUNKS + c) * 2 + 1];
        float n0 = aL.p00 * s0 + aL.p01 * s1 + e0;
        float n1 = aL.p10 * s0 + aL.p11 * s1 + e1;
        s0 = n0; s1 = n1;
    }
}

// packed B position within a 16-k block: (2t,2t+1) then (2t+8,2t+9) adjacent,
// so one uint2 LDS.64 yields the full m16n8k16 B fragment.
__device__ __host__ __forceinline__ int bpos(int q) {
    return (q < 8) ? ((q >> 1) * 4 + (q & 1)) : (((q - 8) >> 1) * 4 + 2 + (q & 1));
}

// ---------------------------------------------------------------------------
// Persistent fused MLP, fp16 m16n8k16 path, zero H smem round-trip.
// 8 warps, warp = 32 tokens = 1 chunk. No __syncthreads in the loop.
// ---------------------------------------------------------------------------
__global__ __launch_bounds__(256, 1) void mlp_kernel(
    const float* __restrict__ in,
    const float* __restrict__ W1, const float* __restrict__ b1,
    const float* __restrict__ W2, const float* __restrict__ b2,
    const float* __restrict__ W3,
    float* __restrict__ out, Aff a)
{
    __shared__ __half sW2h[128 * 144];      // [n][kk*16 + bpos], stride 144 halfs
    __shared__ __half sW1h[128 * 16];       // [n][bpos], stride 16 halfs
    __shared__ float  sB1[128], sB2[128], sW3[256];
    __shared__ float  sScr[8][32][2];       // per-warp layer3 scratch

    const int tid  = threadIdx.x;
    const int w    = tid >> 5;
    const int lane = tid & 31;
    const int gid  = lane >> 2;      // 0..7
    const int tig  = lane & 3;       // 0..3
    const int wbase = w * 32;

    // ---- stage weights (once) ----
    for (int i = tid; i < 128 * 128; i += 256) {
        int k = i >> 7, n = i & 127;
        sW2h[n * 144 + (k >> 4) * 16 + bpos(k & 15)] = __float2half(W2[k * 128 + n]);
    }
    for (int i = tid; i < 128 * 16; i += 256) {
        int n = i >> 4, k = i & 15;
        sW1h[n * 16 + bpos(k)] = __float2half(k < 9 ? W1[k * 128 + n] : 0.f);
    }
    if (tid < 128) { sB1[tid] = b1[tid]; sB2[tid] = b2[tid]; }
    sW3[tid] = W3[tid];
    __syncthreads();

    for (int tile = blockIdx.x; tile < NTILES; tile += GRID) {
        const size_t tok0 = (size_t)tile * TB;

        // ================= layer 1 ===========================================
        // A-frags straight from global (fp16), 1 k16 step, 16 n-tiles.
        uint32_t h16[2][16][2];          // layer1 outputs == layer2 A-frags
        #pragma unroll
        for (int mt = 0; mt < 2; mt++) {
            size_t r0 = tok0 + wbase + mt * 16 + gid;
            size_t r1 = r0 + 8;
            const float* p0 = in + r0 * FEAT + 1;
            const float* p1 = in + r1 * FEAT + 1;
            uint32_t a0 = pack_h2(p0[2 * tig], p0[2 * tig + 1]);
            uint32_t a1 = pack_h2(p1[2 * tig], p1[2 * tig + 1]);
            uint32_t a2 = (tig == 0) ? pack_h2(p0[8], 0.f) : 0u;
            uint32_t a3 = (tig == 0) ? pack_h2(p1[8], 0.f) : 0u;
            #pragma unroll
            for (int nt = 0; nt < 16; nt++) {
                float2 bb = *(const float2*)&sB1[nt * 8 + 2 * tig];
                float c[4] = {bb.x, bb.y, bb.x, bb.y};
                uint2 bw = *(const uint2*)&sW1h[(nt * 8 + gid) * 16 + tig * 4];
                mma_f16(c, a0, a1, a2, a3, bw.x, bw.y);
                h16[mt][nt][0] = tanh_h2(pack_h2(c[0], c[1]));
                h16[mt][nt][1] = tanh_h2(pack_h2(c[2], c[3]));
            }
        }

        // ================= layer 2 + tanh + layer 3 partials =================
        float p[4][2];
        #pragma unroll
        for (int s = 0; s < 4; s++) { p[s][0] = 0.f; p[s][1] = 0.f; }

        #pragma unroll
        for (int half = 0; half < 2; half++) {
            float acc[2][8][4];
            #pragma unroll
            for (int mt = 0; mt < 2; mt++)
                #pragma unroll
                for (int nt = 0; nt < 8; nt++) {
                    float2 bb = *(const float2*)&sB2[(half * 8 + nt) * 8 + 2 * tig];
                    acc[mt][nt][0] = bb.x; acc[mt][nt][1] = bb.y;
                    acc[mt][nt][2] = bb.x; acc[mt][nt][3] = bb.y;
                }
            #pragma unroll
            for (int kk = 0; kk < 8; kk++) {
                #pragma unroll
                for (int nt = 0; nt < 8; nt++) {
                    uint2 bw = *(const uint2*)
                        &sW2h[((half * 8 + nt) * 8 + gid) * 144 + kk * 16 + tig * 4];
                    mma_f16(acc[0][nt], h16[0][2*kk][0], h16[0][2*kk][1],
                            h16[0][2*kk+1][0], h16[0][2*kk+1][1], bw.x, bw.y);
                    mma_f16(acc[1][nt], h16[1][2*kk][0], h16[1][2*kk][1],
                            h16[1][2*kk+1][0], h16[1][2*kk+1][1], bw.x, bw.y);
                }
            }
            // tanh (f32 MUFU) + layer3 partial accumulation
            #pragma unroll
            for (int mt = 0; mt < 2; mt++)
                #pragma unroll
                for (int nt = 0; nt < 8; nt++) {
                    int col = (half * 8 + nt) * 8 + 2 * tig;
                    float4 wv = *(const float4*)&sW3[col * 2];
                    float t0 = fast_tanh(acc[mt][nt][0]);
                    float t1 = fast_tanh(acc[mt][nt][1]);
                    float t2 = fast_tanh(acc[mt][nt][2]);
                    float t3 = fast_tanh(acc[mt][nt][3]);
                    p[2*mt][0]   += t0 * wv.x + t1 * wv.z;
                    p[2*mt][1]   += t0 * wv.y + t1 * wv.w;
                    p[2*mt+1][0] += t2 * wv.x + t3 * wv.z;
                    p[2*mt+1][1] += t2 * wv.y + t3 * wv.w;
                }
        }

        // butterfly-reduce across the 4 lanes of each tig group
        #pragma unroll
        for (int d = 1; d < 4; d <<= 1)
            #pragma unroll
            for (int s = 0; s < 4; s++) {
                p[s][0] += __shfl_xor_sync(0xffffffffu, p[s][0], d);
                p[s][1] += __shfl_xor_sync(0xffffffffu, p[s][1], d);
            }
        // tig==0 lanes own rows {gid, gid+8, gid+16, gid+24}
        if (tig == 0) {
            #pragma unroll
            for (int s = 0; s < 4; s++)
                *(float2*)&sScr[w][gid + s * 8][0] = make_float2(p[s][0], p[s][1]);
        }
        __syncwarp();
        float2 rr = *(const float2*)&sScr[w][lane][0];

        // ================= scan epilogue (warp == chunk) =====================
        {
            size_t tok = tok0 + wbase + lane;
            float uu = in[tok * FEAT];
            float m00 = a.p00, m01 = a.p01, m10 = a.p10, m11 = a.p11;
            float v0 = a.g0 * uu, v1 = a.g1 * uu;
            #pragma unroll
            for (int d = 1; d < 32; d <<= 1) {
                float pm00 = __shfl_up_sync(0xffffffffu, m00, d);
                float pm01 = __shfl_up_sync(0xffffffffu, m01, d);
                float pm10 = __shfl_up_sync(0xffffffffu, m10, d);
                float pm11 = __shfl_up_sync(0xffffffffu, m11, d);
                float pv0  = __shfl_up_sync(0xffffffffu, v0, d);
                float pv1  = __shfl_up_sync(0xffffffffu, v1, d);
                if (lane >= d) {
                    float n00 = m00 * pm00 + m01 * pm10;
                    float n01 = m00 * pm01 + m01 * pm11;
                    float n10 = m10 * pm00 + m11 * pm10;
                    float n11 = m10 * pm01 + m11 * pm11;
                    float nv0 = m00 * pv0 + m01 * pv1 + v0;
                    float nv1 = m10 * pv0 + m11 * pv1 + v1;
                    m00 = n00; m01 = n01; m10 = n10; m11 = n11;
                    v0 = nv0; v1 = nv1;
                }
            }
            float e00 = __shfl_up_sync(0xffffffffu, m00, 1);
            float e01 = __shfl_up_sync(0xffffffffu, m01, 1);
            float e10 = __shfl_up_sync(0xffffffffu, m10, 1);
            float e11 = __shfl_up_sync(0xffffffffu, m11, 1);
            float ev0 = __shfl_up_sync(0xffffffffu, v0, 1);
            float ev1 = __shfl_up_sync(0xffffffffu, v1, 1);
            if (lane == 0) { e00 = 1.f; e01 = 0.f; e10 = 0.f; e11 = 1.f; ev0 = 0.f; ev1 = 0.f; }

            int chunk = tile * 8 + w;
            float2 xs = *(const float2*)&g_X[chunk * 2];
            float s0 = e00 * xs.x + e01 * xs.y + ev0;
            float s1 = e10 * xs.x + e11 * xs.y + ev1;

            *(float2*)&out[tok * 2] = make_float2(s0 + rr.x, s1 + rr.y);
        }
        __syncwarp();   // sScr row reuse next tile
    }
}

// ---------------------------------------------------------------------------
// host: closed-form RK4 affine step (linear ODE), double precision
// ---------------------------------------------------------------------------
static void mat2_mul(const double A[2][2], const double B[2][2], double C[2][2]) {
    C[0][0] = A[0][0]*B[0][0] + A[0][1]*B[1][0];
    C[0][1] = A[0][0]*B[0][1] + A[0][1]*B[1][1];
    C[1][0] = A[1][0]*B[0][0] + A[1][1]*B[1][0];
    C[1][1] = A[1][0]*B[0][1] + A[1][1]*B[1][1];
}

extern "C" void kernel_launch(void* const* d_in, const int* in_sizes, int n_in,
                              void* d_out, int out_size) {
    const float* inp = (const float*)d_in[0];
    const float* x0  = (const float*)d_in[1];
    const float* W1  = (const float*)d_in[2];
    const float* b1  = (const float*)d_in[3];
    const float* W2  = (const float*)d_in[4];
    const float* b2  = (const float*)d_in[5];
    const float* W3  = (const float*)d_in[6];
    float* out = (float*)d_out;

    double A[2][2] = {{-(1.0/TAU_ + K1_), 0.0}, {K1_, -1.0/TAU_}};
    double Bv[2]   = {1.0/TAU_, 0.0};
    double M[2][2] = {{DEL_*A[0][0], DEL_*A[0][1]}, {DEL_*A[1][0], DEL_*A[1][1]}};
    double M2[2][2], M3[2][2], M4[2][2];
    mat2_mul(M, M, M2); mat2_mul(M2, M, M3); mat2_mul(M3, M, M4);
    double Phi[2][2], G[2][2];
    for (int r = 0; r < 2; r++)
        for (int c = 0; c < 2; c++) {
            double id = (r == c) ? 1.0 : 0.0;
            Phi[r][c] = id + M[r][c] + M2[r][c]/2.0 + M3[r][c]/6.0 + M4[r][c]/24.0;
            G[r][c]   = DEL_ * (id + M[r][c]/2.0 + M2[r][c]/6.0 + M3[r][c]/24.0);
        }
    double Gam[2] = {G[0][0]*Bv[0] + G[0][1]*Bv[1], G[1][0]*Bv[0] + G[1][1]*Bv[1]};

    double PL[2][2] = {{Phi[0][0], Phi[0][1]}, {Phi[1][0], Phi[1][1]}};
    for (int s = 0; s < 5; s++) {
        double T[2][2];
        mat2_mul(PL, PL, T);
        PL[0][0]=T[0][0]; PL[0][1]=T[0][1]; PL[1][0]=T[1][0]; PL[1][1]=T[1][1];
    }

    Aff a  = {(float)Phi[0][0], (float)Phi[0][1], (float)Phi[1][0], (float)Phi[1][1],
              (float)Gam[0], (float)Gam[1]};
    Aff aL = {(float)PL[0][0], (float)PL[0][1], (float)PL[1][0], (float)PL[1][1], 0.f, 0.f};

    scan_phase1<<<(NB*CHUNKS + 255)/256, 256>>>(inp, a);
    scan_phase2<<<(NB + 255)/256, 256>>>(x0, aL);

    mlp_kernel<<<GRID, 256>>>(inp, W1, b1, W2, b2, W3, out, a);
}